// round 11
// baseline (speedup 1.0000x reference)
#include <cuda_runtime.h>
#include <math.h>

// ---------------------------------------------------------------------------
// AttentionalGNN: L=18 layers, D=256, H=4 (head dim 64), B=2, N=1024.
// Activations: [b2][C][N] fp32, channel c = d*4 + h.
// Round 11: attention retiled to 32-query tiles (512 blocks, 62KB smem,
// 3 blocks/SM) with direct register->gmem output. GEMM unchanged.
// ---------------------------------------------------------------------------

#define BB   2
#define DD   256
#define NN   1024
#define TEN  (BB*DD*NN)
#define HTEN (BB*512*NN)

// Scratch (device globals). [stream][b2][C][N]
__device__ float g_q  [2*TEN];
__device__ float g_k  [2*TEN];
__device__ float g_v  [2*TEN];
__device__ float g_msg[2*TEN];
__device__ float g_mm [2*TEN];
__device__ float g_h  [2*HTEN];
__device__ float g_stats[2*512*2];

// Pre-split weights (hi/lo), concatenated: Wq|Wk|Wv|Wm|W1|W2
#define SZ_D  (18L*256*256)
#define SZ_1  (18L*512*512)
#define SZ_2  (18L*256*512)
#define OFF_WQ 0L
#define OFF_WK (SZ_D)
#define OFF_WV (2*SZ_D)
#define OFF_WM (3*SZ_D)
#define OFF_W1 (4*SZ_D)
#define OFF_W2 (4*SZ_D + SZ_1)
#define TOTW   (4*SZ_D + SZ_1 + SZ_2)
__device__ float g_whi[TOTW];
__device__ float g_wlo[TOTW];

__device__ __forceinline__ float to_tf32(float x) {
    unsigned u;
    asm("cvt.rna.tf32.f32 %0, %1;" : "=r"(u) : "f"(x));
    return __uint_as_float(u);
}

#define MMA_TF32(acc, af, bf)                                                  \
    asm volatile(                                                              \
        "mma.sync.aligned.m16n8k8.row.col.f32.tf32.tf32.f32 "                  \
        "{%0,%1,%2,%3}, {%4,%5,%6,%7}, {%8,%9}, {%0,%1,%2,%3};"                \
        : "+f"(acc[0]), "+f"(acc[1]), "+f"(acc[2]), "+f"(acc[3])               \
        : "r"(af[0]), "r"(af[1]), "r"(af[2]), "r"(af[3]),                      \
          "r"(bf[0]), "r"(bf[1]))

__device__ __forceinline__ void cpa16(float* dst, const float* src) {
    unsigned sa = (unsigned)__cvta_generic_to_shared(dst);
    asm volatile("cp.async.ca.shared.global [%0], [%1], 16;" :: "r"(sa), "l"(src));
}

// exp on the FMA pipe: round-to-int trick + 2^f poly (deg 6), rel err ~2e-7.
__device__ __forceinline__ float expq(float x) {
    x = fmaxf(x, -80.f);
    float t = fmaf(x, 1.4426950408889634f, 12582912.f);
    float n = t - 12582912.f;
    float f = fmaf(x, 1.4426950408889634f, -n);
    float p = 0.0001540353039338161f;
    p = fmaf(p, f, 0.0013333558146428443f);
    p = fmaf(p, f, 0.009618129107628477f);
    p = fmaf(p, f, 0.05550410866482158f);
    p = fmaf(p, f, 0.2402265069591007f);
    p = fmaf(p, f, 0.6931471805599453f);
    p = fmaf(p, f, 1.0f);
    int ni = __float_as_int(t) - 0x4B400000;
    return __int_as_float(__float_as_int(p) + (ni << 23));
}

// ---------------------------------------------------------------------------
// Weight pre-split
// ---------------------------------------------------------------------------
__global__ __launch_bounds__(256) void presplit_kernel(
    const float* __restrict__ Wq, const float* __restrict__ Wk,
    const float* __restrict__ Wv, const float* __restrict__ Wm,
    const float* __restrict__ W1, const float* __restrict__ W2) {
    long i = ((long)blockIdx.x * 256 + threadIdx.x) * 4;
    if (i >= TOTW) return;
    const float* src; long off = i;
    if      (i < OFF_WK) { src = Wq; }
    else if (i < OFF_WV) { src = Wk; off = i - OFF_WK; }
    else if (i < OFF_WM) { src = Wv; off = i - OFF_WV; }
    else if (i < OFF_W1) { src = Wm; off = i - OFF_WM; }
    else if (i < OFF_W2) { src = W1; off = i - OFF_W1; }
    else                 { src = W2; off = i - OFF_W2; }
    float4 w = *(const float4*)(src + off);
    float4 h, l;
    h.x = to_tf32(w.x); l.x = w.x - h.x;
    h.y = to_tf32(w.y); l.y = w.y - h.y;
    h.z = to_tf32(w.z); l.z = w.z - h.z;
    h.w = to_tf32(w.w); l.w = w.w - h.w;
    *(float4*)(g_whi + i) = h;
    *(float4*)(g_wlo + i) = l;
}

// ---------------------------------------------------------------------------
// Tensor-core GEMM (3xTF32), 2-stage cp.async pipeline (unchanged).
// ---------------------------------------------------------------------------
struct GArgs {
    const float* Whi[3];
    const float* Wlo[3];
    const float* bias[3];
    const float* X0[3][2];
    const float* X1[2];
    const float* res[2];
    const float* bnp[2];
    float*       out[3][2];
    int M, K, K0, use_bn, mtiles;
};

#define GEMM_SMEM (13696 * 4)

__global__ __launch_bounds__(128) void gemm_tc(GArgs a) {
    extern __shared__ __align__(16) float smem[];
    // offsets (floats):  AH: 0 (2x2304) | AL: 4608 | BS: 9216 (2x2176) | BN: 13568 (2x64)

    const int s   = blockIdx.z;
    const int jt  = blockIdx.x;
    const int b2  = jt >> 4;
    const int n0  = (jt & 15) << 6;
    const int mat = blockIdx.y / a.mtiles;
    const int m0  = (blockIdx.y % a.mtiles) << 6;
    const int tid = threadIdx.x;
    const int warp = tid >> 5, lane = tid & 31;
    const int wm = (warp >> 1) << 5;
    const int wn = (warp & 1) << 5;
    const int g = lane >> 2, t = lane & 3;

    const int K = a.K, K0 = a.K0, M = a.M;
    const int use_bn = a.use_bn;
    const float* __restrict__ Whi = a.Whi[mat];
    const float* __restrict__ Wlo = a.Wlo[mat];
    const float* __restrict__ X0  = a.X0[mat][s];
    const float* __restrict__ X1  = a.X1[s];
    const float* __restrict__ bnp = a.bnp[s];

    float acc[2][4][4];
    #pragma unroll
    for (int mi = 0; mi < 2; mi++)
        #pragma unroll
        for (int ni = 0; ni < 4; ni++)
            #pragma unroll
            for (int r = 0; r < 4; r++) acc[mi][ni][r] = 0.f;

    auto load_tile = [&](int k0, int buf) {
        float* AHb = smem + buf * 2304;
        float* ALb = smem + 4608 + buf * 2304;
        float* BSb = smem + 9216 + buf * 2176;
        float* BNb = smem + 13568 + buf * 64;
        #pragma unroll
        for (int e = tid; e < 512; e += 128) {
            int m  = e >> 3;
            int kq = (e & 7) << 2;
            size_t woff = (size_t)(m0 + m) * K + k0 + kq;
            cpa16(AHb + m * 36 + kq, Whi + woff);
            cpa16(ALb + m * 36 + kq, Wlo + woff);
        }
        #pragma unroll
        for (int e = tid; e < 512; e += 128) {
            int kk = e >> 4;
            int nq = (e & 15) << 2;
            int k = k0 + kk;
            const float* src = (k < K0)
                ? X0 + ((size_t)b2 * K0 + k) * NN + n0 + nq
                : X1 + ((size_t)b2 * (K - K0) + (k - K0)) * NN + n0 + nq;
            cpa16(BSb + kk * 68 + nq, src);
        }
        if (use_bn && tid < 64) BNb[tid] = bnp[2 * k0 + tid];
        asm volatile("cp.async.commit_group;" ::: "memory");
    };

    const int niter = K >> 5;
    load_tile(0, 0);

    for (int it = 0; it < niter; it++) {
        const int buf = it & 1;
        if (it + 1 < niter) {
            load_tile((it + 1) << 5, buf ^ 1);
            asm volatile("cp.async.wait_group 1;" ::: "memory");
        } else {
            asm volatile("cp.async.wait_group 0;" ::: "memory");
        }
        __syncthreads();

        const float* AHb = smem + buf * 2304;
        const float* ALb = smem + 4608 + buf * 2304;
        const float* BSb = smem + 9216 + buf * 2176;
        const float* BNb = smem + 13568 + buf * 64;

        #pragma unroll
        for (int kk = 0; kk < 32; kk += 8) {
            unsigned afh[2][4], afl[2][4];
            #pragma unroll
            for (int mi = 0; mi < 2; mi++) {
                int r0 = wm + mi * 16 + g;
                afh[mi][0] = __float_as_uint(AHb[(r0    ) * 36 + kk + t    ]);
                afh[mi][1] = __float_as_uint(AHb[(r0 + 8) * 36 + kk + t    ]);
                afh[mi][2] = __float_as_uint(AHb[(r0    ) * 36 + kk + t + 4]);
                afh[mi][3] = __float_as_uint(AHb[(r0 + 8) * 36 + kk + t + 4]);
                afl[mi][0] = __float_as_uint(ALb[(r0    ) * 36 + kk + t    ]);
                afl[mi][1] = __float_as_uint(ALb[(r0 + 8) * 36 + kk + t    ]);
                afl[mi][2] = __float_as_uint(ALb[(r0    ) * 36 + kk + t + 4]);
                afl[mi][3] = __float_as_uint(ALb[(r0 + 8) * 36 + kk + t + 4]);
            }
            float sc0 = 1.f, sh0 = 0.f, sc1 = 1.f, sh1 = 0.f;
            if (use_bn) {
                sc0 = BNb[2 * (kk + t)];     sh0 = BNb[2 * (kk + t) + 1];
                sc1 = BNb[2 * (kk + t + 4)]; sh1 = BNb[2 * (kk + t + 4) + 1];
            }
            #pragma unroll
            for (int ni = 0; ni < 4; ni++) {
                int c = wn + ni * 8 + g;
                float b0 = BSb[(kk + t    ) * 68 + c];
                float b1 = BSb[(kk + t + 4) * 68 + c];
                if (use_bn) {
                    b0 = fmaxf(fmaf(b0, sc0, sh0), 0.f);
                    b1 = fmaxf(fmaf(b1, sc1, sh1), 0.f);
                }
                float h0 = to_tf32(b0), h1 = to_tf32(b1);
                unsigned bh2[2] = {__float_as_uint(h0), __float_as_uint(h1)};
                unsigned bl2[2] = {__float_as_uint(b0 - h0), __float_as_uint(b1 - h1)};
                #pragma unroll
                for (int mi = 0; mi < 2; mi++) {
                    MMA_TF32(acc[mi][ni], afh[mi], bl2);
                    MMA_TF32(acc[mi][ni], afl[mi], bh2);
                    MMA_TF32(acc[mi][ni], afh[mi], bh2);
                }
            }
        }
        __syncthreads();
    }

    const float* resp = a.res[s];
    const float* biasp = a.bias[mat];
    float* outp = a.out[mat][s];
    #pragma unroll
    for (int mi = 0; mi < 2; mi++) {
        #pragma unroll
        for (int half = 0; half < 2; half++) {
            int m = m0 + wm + mi * 16 + g + half * 8;
            float bb = biasp[m];
            #pragma unroll
            for (int ni = 0; ni < 4; ni++) {
                int col = n0 + wn + ni * 8 + 2 * t;
                size_t off = ((size_t)b2 * M + m) * NN + col;
                float2 c;
                c.x = acc[mi][ni][2 * half + 0] + bb;
                c.y = acc[mi][ni][2 * half + 1] + bb;
                if (resp) {
                    float2 r = *(const float2*)(resp + off);
                    c.x += r.x; c.y += r.y;
                }
                *(float2*)(outp + off) = c;
            }
        }
    }
}

// ---------------------------------------------------------------------------
// Tensor-core flash attention (3xTF32), 32-query tiles.
// grid = (32 qtiles, 8 = b2*4+h, 2 streams), 256 threads = 8 warps.
// Warps: qw = warp>>2 (2 x 16q), kw = warp&3 (4 x 16k in S / 16d in PV).
// Smem (floats): Qh[64][36] | Ql[64][36] | Ks[64][68] | Vs[64][68] | Ps[32][68]
//   = 2304+2304+4352+4352+2176 = 15488 floats = 61952 B  -> 3 blocks/SM.
// Output written directly from registers to gmem.
// ---------------------------------------------------------------------------
#define ATTN_SMEM (15488 * 4)

__global__ __launch_bounds__(256) void attn_kernel() {
    extern __shared__ __align__(16) float sm[];
    float* Qh = sm;                 // [d][q] stride 36, hi (scaled)
    float* Ql = sm + 2304;          // [d][q] stride 36, lo
    float* Ks = sm + 4608;          // [d][k] stride 68
    float* Vs = sm + 8960;          // [d][k] stride 68
    float* Ps = sm + 13312;         // [q][k] stride 68, raw P
    __shared__ float red_max[4][2][16];
    __shared__ float red_sum[4][2][16];

    const int qt = blockIdx.x;          // 0..31
    const int bh = blockIdx.y;
    const int s  = blockIdx.z;
    const int b2 = bh >> 2, h = bh & 3;
    const int q0 = qt << 5;
    const int tid = threadIdx.x;
    const int warp = tid >> 5, lane = tid & 31;
    const int g = lane >> 2, t = lane & 3;
    const int qw = warp >> 2;           // 0..1
    const int kw = warp & 3;            // 0..3
    const int qrow = qw << 4;           // warp q base (0/16)
    const int kcol = kw << 4;           // warp k base (S) == warp d base (PV)

    size_t base = (size_t)s * TEN + (size_t)b2 * (DD * NN);
    const float* __restrict__ qp = g_q + base;
    const float* __restrict__ kp = g_k + base;
    const float* __restrict__ vp = g_v + base;
    float* mp = g_msg + base;

    // load Q tile [d][q] (32 q), fold 1/8 scale, split once
    for (int e = tid; e < 2048; e += 256) {
        int qi = e & 31, d = e >> 5;
        float v = qp[(size_t)(d * 4 + h) * NN + q0 + qi] * 0.125f;
        float hi = to_tf32(v);
        Qh[d * 36 + qi] = hi;
        Ql[d * 36 + qi] = v - hi;
    }

    float oacc[2][4] = {};
    float mi2[2] = {-1e30f, -1e30f};
    float li2[2] = {0.f, 0.f};

    for (int kt = 0; kt < 16; kt++) {
        int m0k = kt << 6;
        __syncthreads();   // prev iter done reading Ks/Vs/Ps
        for (int e = tid; e < 1024; e += 256) {
            int d  = e >> 4;
            int c4 = (e & 15) << 2;
            size_t goff = (size_t)(d * 4 + h) * NN + m0k + c4;
            cpa16(Ks + d * 68 + c4, kp + goff);
            cpa16(Vs + d * 68 + c4, vp + goff);
        }
        asm volatile("cp.async.commit_group;\n\tcp.async.wait_group 0;" ::: "memory");
        __syncthreads();

        // ----- S = Q^T K (3xTF32), warp tile 16q x 16k -----
        float sacc[2][4] = {};
        #pragma unroll
        for (int kk = 0; kk < 64; kk += 8) {
            unsigned ah[4], al[4];
            ah[0] = __float_as_uint(Qh[(kk + t    ) * 36 + qrow + g    ]);
            ah[1] = __float_as_uint(Qh[(kk + t    ) * 36 + qrow + g + 8]);
            ah[2] = __float_as_uint(Qh[(kk + t + 4) * 36 + qrow + g    ]);
            ah[3] = __float_as_uint(Qh[(kk + t + 4) * 36 + qrow + g + 8]);
            al[0] = __float_as_uint(Ql[(kk + t    ) * 36 + qrow + g    ]);
            al[1] = __float_as_uint(Ql[(kk + t    ) * 36 + qrow + g + 8]);
            al[2] = __float_as_uint(Ql[(kk + t + 4) * 36 + qrow + g    ]);
            al[3] = __float_as_uint(Ql[(kk + t + 4) * 36 + qrow + g + 8]);
            #pragma unroll
            for (int ni = 0; ni < 2; ni++) {
                int c = kcol + ni * 8 + g;
                float b0 = Ks[(kk + t    ) * 68 + c];
                float b1 = Ks[(kk + t + 4) * 68 + c];
                float h0 = to_tf32(b0), h1 = to_tf32(b1);
                unsigned bh2[2] = {__float_as_uint(h0), __float_as_uint(h1)};
                unsigned bl2[2] = {__float_as_uint(b0 - h0), __float_as_uint(b1 - h1)};
                MMA_TF32(sacc[ni], ah, bl2);
                MMA_TF32(sacc[ni], al, bh2);
                MMA_TF32(sacc[ni], ah, bh2);
            }
        }

        // ----- online softmax (rows: r=0 -> qrow+g, r=1 -> qrow+g+8) -----
        float mloc[2] = {-1e30f, -1e30f};
        #pragma unroll
        for (int ni = 0; ni < 2; ni++) {
            mloc[0] = fmaxf(mloc[0], fmaxf(sacc[ni][0], sacc[ni][1]));
            mloc[1] = fmaxf(mloc[1], fmaxf(sacc[ni][2], sacc[ni][3]));
        }
        #pragma unroll
        for (int r = 0; r < 2; r++) {
            mloc[r] = fmaxf(mloc[r], __shfl_xor_sync(0xffffffffu, mloc[r], 1));
            mloc[r] = fmaxf(mloc[r], __shfl_xor_sync(0xffffffffu, mloc[r], 2));
        }
        if (t == 0) {
            red_max[kw][qw][g    ] = mloc[0];
            red_max[kw][qw][g + 8] = mloc[1];
        }
        __syncthreads();
        float mn[2], alpha[2];
        #pragma unroll
        for (int r = 0; r < 2; r++) {
            int row = g + r * 8;
            float mk = fmaxf(fmaxf(red_max[0][qw][row], red_max[1][qw][row]),
                             fmaxf(red_max[2][qw][row], red_max[3][qw][row]));
            mn[r] = fmaxf(mi2[r], mk);
            alpha[r] = expq(mi2[r] - mn[r]);
            mi2[r] = mn[r];
        }
        float rs[2] = {0.f, 0.f};
        #pragma unroll
        for (int ni = 0; ni < 2; ni++) {
            #pragma unroll
            for (int j = 0; j < 4; j++) {
                int r = j >> 1;
                float p = expq(sacc[ni][j] - mn[r]);
                sacc[ni][j] = p;
                rs[r] += p;
            }
        }
        #pragma unroll
        for (int r = 0; r < 2; r++) {
            rs[r] += __shfl_xor_sync(0xffffffffu, rs[r], 1);
            rs[r] += __shfl_xor_sync(0xffffffffu, rs[r], 2);
        }
        if (t == 0) {
            red_sum[kw][qw][g    ] = rs[0];
            red_sum[kw][qw][g + 8] = rs[1];
        }
        // stage raw P [q][k]
        #pragma unroll
        for (int ni = 0; ni < 2; ni++) {
            #pragma unroll
            for (int r = 0; r < 2; r++) {
                int row = qrow + g + r * 8;
                int col = kcol + ni * 8 + 2 * t;
                *(float2*)(Ps + row * 68 + col) =
                    make_float2(sacc[ni][2 * r], sacc[ni][2 * r + 1]);
            }
        }
        __syncthreads();
        #pragma unroll
        for (int r = 0; r < 2; r++) {
            int row = g + r * 8;
            float rstot = (red_sum[0][qw][row] + red_sum[1][qw][row])
                        + (red_sum[2][qw][row] + red_sum[3][qw][row]);
            li2[r] = li2[r] * alpha[r] + rstot;
        }
        // rescale O
        #pragma unroll
        for (int ni = 0; ni < 2; ni++) {
            oacc[ni][0] *= alpha[0]; oacc[ni][1] *= alpha[0];
            oacc[ni][2] *= alpha[1]; oacc[ni][3] *= alpha[1];
        }

        // ----- O += P V (3xTF32), warp tile 16q x 16d, full 64 k -----
        #pragma unroll
        for (int kk = 0; kk < 64; kk += 8) {
            float a0 = Ps[(qrow + g    ) * 68 + kk + t    ];
            float a1 = Ps[(qrow + g + 8) * 68 + kk + t    ];
            float a2 = Ps[(qrow + g    ) * 68 + kk + t + 4];
            float a3 = Ps[(qrow + g + 8) * 68 + kk + t + 4];
            float ah0 = to_tf32(a0), ah1 = to_tf32(a1);
            float ah2 = to_tf32(a2), ah3 = to_tf32(a3);
            unsigned ah[4] = {__float_as_uint(ah0), __float_as_uint(ah1),
                              __float_as_uint(ah2), __float_as_uint(ah3)};
            unsigned al[4] = {__float_as_uint(a0 - ah0), __float_as_uint(a1 - ah1),
                              __float_as_uint(a2 - ah2), __float_as_uint(a3 - ah3)};
            #pragma unroll
            for (int ni = 0; ni < 2; ni++) {
                int c = kcol + ni * 8 + g;   // d column
                float b0 = Vs[c * 68 + kk + t    ];
                float b1 = Vs[c * 68 + kk + t + 4];
                float h0 = to_tf32(b0), h1 = to_tf32(b1);
                unsigned bh2[2] = {__float_as_uint(h0), __float_as_uint(h1)};
                unsigned bl2[2] = {__float_as_uint(b0 - h0), __float_as_uint(b1 - h1)};
                MMA_TF32(oacc[ni], ah, bl2);
                MMA_TF32(oacc[ni], al, bh2);
                MMA_TF32(oacc[ni], ah, bh2);
            }
        }
    }

    // ----- finalize: divide by li and store directly to gmem -----
    float inv[2] = {1.f / li2[0], 1.f / li2[1]};
    #pragma unroll
    for (int ni = 0; ni < 2; ni++) {
        #pragma unroll
        for (int j = 0; j < 4; j++) {
            int r = j >> 1;
            int q = q0 + qrow + g + r * 8;
            int d = kcol + ni * 8 + 2 * t + (j & 1);
            mp[(size_t)(d * 4 + h) * NN + q] = oacc[ni][j] * inv[r];
        }
    }
}

// ---------------------------------------------------------------------------
// BatchNorm stats (unchanged).
// ---------------------------------------------------------------------------
__global__ __launch_bounds__(256) void bn_stats_kernel(const float* __restrict__ g1,
                                                       const float* __restrict__ be1) {
    const int c = blockIdx.x;
    const int s = blockIdx.y;
    const float* hp = g_h + (size_t)s * HTEN;
    int tid = threadIdx.x;
    float sum = 0.f, sq = 0.f;
    for (int idx = tid; idx < 2048; idx += 256) {
        int b2 = idx >> 10, n = idx & 1023;
        float v = hp[((size_t)b2 * 512 + c) * NN + n];
        sum += v;
        sq = fmaf(v, v, sq);
    }
    #pragma unroll
    for (int w = 16; w; w >>= 1) {
        sum += __shfl_xor_sync(0xffffffffu, sum, w);
        sq  += __shfl_xor_sync(0xffffffffu, sq,  w);
    }
    __shared__ float ssum[8], ssq[8];
    int wid = tid >> 5, lane = tid & 31;
    if (lane == 0) { ssum[wid] = sum; ssq[wid] = sq; }
    __syncthreads();
    if (tid == 0) {
        float S = 0.f, Q = 0.f;
        #pragma unroll
        for (int i = 0; i < 8; i++) { S += ssum[i]; Q += ssq[i]; }
        float mean = S * (1.f / 2048.f);
        float var  = Q * (1.f / 2048.f) - mean * mean;
        float rstd = rsqrtf(var + 1e-5f);
        float sc = rstd * g1[c];
        float sh = be1[c] - mean * sc;
        g_stats[(s * 512 + c) * 2 + 0] = sc;
        g_stats[(s * 512 + c) * 2 + 1] = sh;
    }
}

// ---------------------------------------------------------------------------
// Host orchestration
// ---------------------------------------------------------------------------
extern "C" void kernel_launch(void* const* d_in, const int* in_sizes, int n_in,
                              void* d_out, int out_size) {
    const float* desc0 = (const float*)d_in[0];
    const float* desc1 = (const float*)d_in[1];
    const float* Wq  = (const float*)d_in[2];
    const float* bq  = (const float*)d_in[3];
    const float* Wk  = (const float*)d_in[4];
    const float* bk  = (const float*)d_in[5];
    const float* Wv  = (const float*)d_in[6];
    const float* bv  = (const float*)d_in[7];
    const float* Wm  = (const float*)d_in[8];
    const float* bm  = (const float*)d_in[9];
    const float* W1  = (const float*)d_in[10];
    const float* b1  = (const float*)d_in[11];
    const float* g1  = (const float*)d_in[12];
    const float* be1 = (const float*)d_in[13];
    const float* W2  = (const float*)d_in[14];
    const float* b2  = (const float*)d_in[15];
    float* out = (float*)d_out;

    float *qb, *kb, *vb, *msgb, *mmb, *hb, *statsb, *whi, *wlo;
    cudaGetSymbolAddress((void**)&qb,    g_q);
    cudaGetSymbolAddress((void**)&kb,    g_k);
    cudaGetSymbolAddress((void**)&vb,    g_v);
    cudaGetSymbolAddress((void**)&msgb,  g_msg);
    cudaGetSymbolAddress((void**)&mmb,   g_mm);
    cudaGetSymbolAddress((void**)&hb,    g_h);
    cudaGetSymbolAddress((void**)&statsb, g_stats);
    cudaGetSymbolAddress((void**)&whi,   g_whi);
    cudaGetSymbolAddress((void**)&wlo,   g_wlo);

    cudaFuncSetAttribute(attn_kernel,
                         cudaFuncAttributeMaxDynamicSharedMemorySize, ATTN_SMEM);
    cudaFuncSetAttribute(gemm_tc,
                         cudaFuncAttributeMaxDynamicSharedMemorySize, GEMM_SMEM);

    presplit_kernel<<<(int)((TOTW / 4 + 255) / 256), 256>>>(Wq, Wk, Wv, Wm, W1, W2);

    cudaMemcpyAsync(out + 2 * (size_t)TEN, desc0, TEN * sizeof(float),
                    cudaMemcpyDeviceToDevice, 0);
    cudaMemcpyAsync(out + 3 * (size_t)TEN, desc1, TEN * sizeof(float),
                    cudaMemcpyDeviceToDevice, 0);

    const float* xa = desc0;
    const float* xb = desc1;

    for (int i = 0; i < 18; i++) {
        const float *sa, *sb, *ra, *rb;
        float *oa, *ob;
        if (i == 0) {
            sa = xa; sb = xb; ra = desc0; rb = desc1;
            oa = out;            ob = out + (size_t)TEN;
        } else if (i == 1) {
            sa = xb; sb = xa; ra = desc0; rb = desc1;
            oa = out + 4 * (size_t)TEN; ob = out + 5 * (size_t)TEN;
        } else {
            if ((i & 1) == 0) { sa = xa; sb = xb; }
            else              { sa = xb; sb = xa; }
            ra = xa; rb = xb;
            oa = out + (size_t)(2 + 2 * i) * TEN;
            ob = oa + (size_t)TEN;
        }

        const float* Wq_hi = whi + OFF_WQ + (size_t)i * 65536;
        const float* Wq_lo = wlo + OFF_WQ + (size_t)i * 65536;
        const float* Wk_hi = whi + OFF_WK + (size_t)i * 65536;
        const float* Wk_lo = wlo + OFF_WK + (size_t)i * 65536;
        const float* Wv_hi = whi + OFF_WV + (size_t)i * 65536;
        const float* Wv_lo = wlo + OFF_WV + (size_t)i * 65536;
        const float* Wm_hi = whi + OFF_WM + (size_t)i * 65536;
        const float* Wm_lo = wlo + OFF_WM + (size_t)i * 65536;
        const float* W1_hi = whi + OFF_W1 + (size_t)i * 262144;
        const float* W1_lo = wlo + OFF_W1 + (size_t)i * 262144;
        const float* W2_hi = whi + OFF_W2 + (size_t)i * 131072;
        const float* W2_lo = wlo + OFF_W2 + (size_t)i * 131072;
        const float* bq_i = bq + (size_t)i * 256;
        const float* bk_i = bk + (size_t)i * 256;
        const float* bv_i = bv + (size_t)i * 256;
        const float* bm_i = bm + (size_t)i * 256;
        const float* b1_i = b1 + (size_t)i * 512;
        const float* b2_i = b2 + (size_t)i * 256;
        const float* g1_i = g1 + (size_t)i * 512;
        const float* be_i = be1 + (size_t)i * 512;

        GArgs ga = {};
        ga.bnp[0] = statsb; ga.bnp[1] = statsb + 1024;

        // q/k/v merged
        ga.Whi[0] = Wq_hi; ga.Wlo[0] = Wq_lo; ga.bias[0] = bq_i;
        ga.Whi[1] = Wk_hi; ga.Wlo[1] = Wk_lo; ga.bias[1] = bk_i;
        ga.Whi[2] = Wv_hi; ga.Wlo[2] = Wv_lo; ga.bias[2] = bv_i;
        ga.X0[0][0] = xa; ga.X0[0][1] = xb;
        ga.X0[1][0] = sa; ga.X0[1][1] = sb;
        ga.X0[2][0] = sa; ga.X0[2][1] = sb;
        ga.out[0][0] = qb; ga.out[0][1] = qb + TEN;
        ga.out[1][0] = kb; ga.out[1][1] = kb + TEN;
        ga.out[2][0] = vb; ga.out[2][1] = vb + TEN;
        ga.X1[0] = ga.X1[1] = nullptr;
        ga.res[0] = ga.res[1] = nullptr;
        ga.M = 256; ga.K = 256; ga.K0 = 256; ga.use_bn = 0; ga.mtiles = 4;
        gemm_tc<<<dim3(32, 12, 2), 128, GEMM_SMEM>>>(ga);

        // attention
        attn_kernel<<<dim3(32, 8, 2), 256, ATTN_SMEM>>>();

        // msg projection
        ga.Whi[0] = Wm_hi; ga.Wlo[0] = Wm_lo; ga.bias[0] = bm_i;
        ga.X0[0][0] = msgb; ga.X0[0][1] = msgb + TEN;
        ga.out[0][0] = mmb; ga.out[0][1] = mmb + TEN;
        ga.M = 256; ga.K = 256; ga.K0 = 256; ga.use_bn = 0; ga.mtiles = 4;
        gemm_tc<<<dim3(32, 4, 2), 128, GEMM_SMEM>>>(ga);

        // h = W1 [x; msg] + b1
        ga.Whi[0] = W1_hi; ga.Wlo[0] = W1_lo; ga.bias[0] = b1_i;
        ga.X0[0][0] = xa; ga.X0[0][1] = xb;
        ga.X1[0] = mmb; ga.X1[1] = mmb + TEN;
        ga.out[0][0] = hb; ga.out[0][1] = hb + HTEN;
        ga.M = 512; ga.K = 512; ga.K0 = 256; ga.use_bn = 0; ga.mtiles = 8;
        gemm_tc<<<dim3(32, 8, 2), 128, GEMM_SMEM>>>(ga);

        // BN stats
        bn_stats_kernel<<<dim3(512, 2), 256>>>(g1_i, be_i);

        // out = res + W2 relu(BN(h)) + b2
        ga.Whi[0] = W2_hi; ga.Wlo[0] = W2_lo; ga.bias[0] = b2_i;
        ga.X0[0][0] = hb; ga.X0[0][1] = hb + HTEN;
        ga.X1[0] = ga.X1[1] = nullptr;
        ga.res[0] = ra; ga.res[1] = rb;
        ga.out[0][0] = oa; ga.out[0][1] = ob;
        ga.M = 256; ga.K = 512; ga.K0 = 512; ga.use_bn = 1; ga.mtiles = 4;
        gemm_tc<<<dim3(32, 4, 2), 128, GEMM_SMEM>>>(ga);
        ga.res[0] = ga.res[1] = nullptr;

        xa = oa; xb = ob;
    }
}

// round 12
// speedup vs baseline: 1.0711x; 1.0711x over previous
#include <cuda_runtime.h>
#include <math.h>

// ---------------------------------------------------------------------------
// AttentionalGNN: L=18 layers, D=256, H=4 (head dim 64), B=2, N=1024.
// Activations: [b2][C][N] fp32, channel c = d*4 + h.
// Round 12: revert attention to 64-q tiles (round-10 structure) and add
// software pipelining: K double-buffered, V single-buffered, cp.async with
// wait_group 1 (no full-stop waits). GEMM unchanged from round 7.
// ---------------------------------------------------------------------------

#define BB   2
#define DD   256
#define NN   1024
#define TEN  (BB*DD*NN)
#define HTEN (BB*512*NN)

// Scratch (device globals). [stream][b2][C][N]
__device__ float g_q  [2*TEN];
__device__ float g_k  [2*TEN];
__device__ float g_v  [2*TEN];
__device__ float g_msg[2*TEN];
__device__ float g_mm [2*TEN];
__device__ float g_h  [2*HTEN];
__device__ float g_stats[2*512*2];

// Pre-split weights (hi/lo), concatenated: Wq|Wk|Wv|Wm|W1|W2
#define SZ_D  (18L*256*256)
#define SZ_1  (18L*512*512)
#define SZ_2  (18L*256*512)
#define OFF_WQ 0L
#define OFF_WK (SZ_D)
#define OFF_WV (2*SZ_D)
#define OFF_WM (3*SZ_D)
#define OFF_W1 (4*SZ_D)
#define OFF_W2 (4*SZ_D + SZ_1)
#define TOTW   (4*SZ_D + SZ_1 + SZ_2)
__device__ float g_whi[TOTW];
__device__ float g_wlo[TOTW];

__device__ __forceinline__ float to_tf32(float x) {
    unsigned u;
    asm("cvt.rna.tf32.f32 %0, %1;" : "=r"(u) : "f"(x));
    return __uint_as_float(u);
}

#define MMA_TF32(acc, af, bf)                                                  \
    asm volatile(                                                              \
        "mma.sync.aligned.m16n8k8.row.col.f32.tf32.tf32.f32 "                  \
        "{%0,%1,%2,%3}, {%4,%5,%6,%7}, {%8,%9}, {%0,%1,%2,%3};"                \
        : "+f"(acc[0]), "+f"(acc[1]), "+f"(acc[2]), "+f"(acc[3])               \
        : "r"(af[0]), "r"(af[1]), "r"(af[2]), "r"(af[3]),                      \
          "r"(bf[0]), "r"(bf[1]))

__device__ __forceinline__ void cpa16(float* dst, const float* src) {
    unsigned sa = (unsigned)__cvta_generic_to_shared(dst);
    asm volatile("cp.async.ca.shared.global [%0], [%1], 16;" :: "r"(sa), "l"(src));
}

// exp on the FMA pipe: round-to-int trick + 2^f poly (deg 6), rel err ~2e-7.
__device__ __forceinline__ float expq(float x) {
    x = fmaxf(x, -80.f);
    float t = fmaf(x, 1.4426950408889634f, 12582912.f);
    float n = t - 12582912.f;
    float f = fmaf(x, 1.4426950408889634f, -n);
    float p = 0.0001540353039338161f;
    p = fmaf(p, f, 0.0013333558146428443f);
    p = fmaf(p, f, 0.009618129107628477f);
    p = fmaf(p, f, 0.05550410866482158f);
    p = fmaf(p, f, 0.2402265069591007f);
    p = fmaf(p, f, 0.6931471805599453f);
    p = fmaf(p, f, 1.0f);
    int ni = __float_as_int(t) - 0x4B400000;
    return __int_as_float(__float_as_int(p) + (ni << 23));
}

// ---------------------------------------------------------------------------
// Weight pre-split
// ---------------------------------------------------------------------------
__global__ __launch_bounds__(256) void presplit_kernel(
    const float* __restrict__ Wq, const float* __restrict__ Wk,
    const float* __restrict__ Wv, const float* __restrict__ Wm,
    const float* __restrict__ W1, const float* __restrict__ W2) {
    long i = ((long)blockIdx.x * 256 + threadIdx.x) * 4;
    if (i >= TOTW) return;
    const float* src; long off = i;
    if      (i < OFF_WK) { src = Wq; }
    else if (i < OFF_WV) { src = Wk; off = i - OFF_WK; }
    else if (i < OFF_WM) { src = Wv; off = i - OFF_WV; }
    else if (i < OFF_W1) { src = Wm; off = i - OFF_WM; }
    else if (i < OFF_W2) { src = W1; off = i - OFF_W1; }
    else                 { src = W2; off = i - OFF_W2; }
    float4 w = *(const float4*)(src + off);
    float4 h, l;
    h.x = to_tf32(w.x); l.x = w.x - h.x;
    h.y = to_tf32(w.y); l.y = w.y - h.y;
    h.z = to_tf32(w.z); l.z = w.z - h.z;
    h.w = to_tf32(w.w); l.w = w.w - h.w;
    *(float4*)(g_whi + i) = h;
    *(float4*)(g_wlo + i) = l;
}

// ---------------------------------------------------------------------------
// Tensor-core GEMM (3xTF32), 2-stage cp.async pipeline (unchanged).
// ---------------------------------------------------------------------------
struct GArgs {
    const float* Whi[3];
    const float* Wlo[3];
    const float* bias[3];
    const float* X0[3][2];
    const float* X1[2];
    const float* res[2];
    const float* bnp[2];
    float*       out[3][2];
    int M, K, K0, use_bn, mtiles;
};

#define GEMM_SMEM (13696 * 4)

__global__ __launch_bounds__(128) void gemm_tc(GArgs a) {
    extern __shared__ __align__(16) float smem[];
    // offsets (floats):  AH: 0 (2x2304) | AL: 4608 | BS: 9216 (2x2176) | BN: 13568 (2x64)

    const int s   = blockIdx.z;
    const int jt  = blockIdx.x;
    const int b2  = jt >> 4;
    const int n0  = (jt & 15) << 6;
    const int mat = blockIdx.y / a.mtiles;
    const int m0  = (blockIdx.y % a.mtiles) << 6;
    const int tid = threadIdx.x;
    const int warp = tid >> 5, lane = tid & 31;
    const int wm = (warp >> 1) << 5;
    const int wn = (warp & 1) << 5;
    const int g = lane >> 2, t = lane & 3;

    const int K = a.K, K0 = a.K0, M = a.M;
    const int use_bn = a.use_bn;
    const float* __restrict__ Whi = a.Whi[mat];
    const float* __restrict__ Wlo = a.Wlo[mat];
    const float* __restrict__ X0  = a.X0[mat][s];
    const float* __restrict__ X1  = a.X1[s];
    const float* __restrict__ bnp = a.bnp[s];

    float acc[2][4][4];
    #pragma unroll
    for (int mi = 0; mi < 2; mi++)
        #pragma unroll
        for (int ni = 0; ni < 4; ni++)
            #pragma unroll
            for (int r = 0; r < 4; r++) acc[mi][ni][r] = 0.f;

    auto load_tile = [&](int k0, int buf) {
        float* AHb = smem + buf * 2304;
        float* ALb = smem + 4608 + buf * 2304;
        float* BSb = smem + 9216 + buf * 2176;
        float* BNb = smem + 13568 + buf * 64;
        #pragma unroll
        for (int e = tid; e < 512; e += 128) {
            int m  = e >> 3;
            int kq = (e & 7) << 2;
            size_t woff = (size_t)(m0 + m) * K + k0 + kq;
            cpa16(AHb + m * 36 + kq, Whi + woff);
            cpa16(ALb + m * 36 + kq, Wlo + woff);
        }
        #pragma unroll
        for (int e = tid; e < 512; e += 128) {
            int kk = e >> 4;
            int nq = (e & 15) << 2;
            int k = k0 + kk;
            const float* src = (k < K0)
                ? X0 + ((size_t)b2 * K0 + k) * NN + n0 + nq
                : X1 + ((size_t)b2 * (K - K0) + (k - K0)) * NN + n0 + nq;
            cpa16(BSb + kk * 68 + nq, src);
        }
        if (use_bn && tid < 64) BNb[tid] = bnp[2 * k0 + tid];
        asm volatile("cp.async.commit_group;" ::: "memory");
    };

    const int niter = K >> 5;
    load_tile(0, 0);

    for (int it = 0; it < niter; it++) {
        const int buf = it & 1;
        if (it + 1 < niter) {
            load_tile((it + 1) << 5, buf ^ 1);
            asm volatile("cp.async.wait_group 1;" ::: "memory");
        } else {
            asm volatile("cp.async.wait_group 0;" ::: "memory");
        }
        __syncthreads();

        const float* AHb = smem + buf * 2304;
        const float* ALb = smem + 4608 + buf * 2304;
        const float* BSb = smem + 9216 + buf * 2176;
        const float* BNb = smem + 13568 + buf * 64;

        #pragma unroll
        for (int kk = 0; kk < 32; kk += 8) {
            unsigned afh[2][4], afl[2][4];
            #pragma unroll
            for (int mi = 0; mi < 2; mi++) {
                int r0 = wm + mi * 16 + g;
                afh[mi][0] = __float_as_uint(AHb[(r0    ) * 36 + kk + t    ]);
                afh[mi][1] = __float_as_uint(AHb[(r0 + 8) * 36 + kk + t    ]);
                afh[mi][2] = __float_as_uint(AHb[(r0    ) * 36 + kk + t + 4]);
                afh[mi][3] = __float_as_uint(AHb[(r0 + 8) * 36 + kk + t + 4]);
                afl[mi][0] = __float_as_uint(ALb[(r0    ) * 36 + kk + t    ]);
                afl[mi][1] = __float_as_uint(ALb[(r0 + 8) * 36 + kk + t    ]);
                afl[mi][2] = __float_as_uint(ALb[(r0    ) * 36 + kk + t + 4]);
                afl[mi][3] = __float_as_uint(ALb[(r0 + 8) * 36 + kk + t + 4]);
            }
            float sc0 = 1.f, sh0 = 0.f, sc1 = 1.f, sh1 = 0.f;
            if (use_bn) {
                sc0 = BNb[2 * (kk + t)];     sh0 = BNb[2 * (kk + t) + 1];
                sc1 = BNb[2 * (kk + t + 4)]; sh1 = BNb[2 * (kk + t + 4) + 1];
            }
            #pragma unroll
            for (int ni = 0; ni < 4; ni++) {
                int c = wn + ni * 8 + g;
                float b0 = BSb[(kk + t    ) * 68 + c];
                float b1 = BSb[(kk + t + 4) * 68 + c];
                if (use_bn) {
                    b0 = fmaxf(fmaf(b0, sc0, sh0), 0.f);
                    b1 = fmaxf(fmaf(b1, sc1, sh1), 0.f);
                }
                float h0 = to_tf32(b0), h1 = to_tf32(b1);
                unsigned bh2[2] = {__float_as_uint(h0), __float_as_uint(h1)};
                unsigned bl2[2] = {__float_as_uint(b0 - h0), __float_as_uint(b1 - h1)};
                #pragma unroll
                for (int mi = 0; mi < 2; mi++) {
                    MMA_TF32(acc[mi][ni], afh[mi], bl2);
                    MMA_TF32(acc[mi][ni], afl[mi], bh2);
                    MMA_TF32(acc[mi][ni], afh[mi], bh2);
                }
            }
        }
        __syncthreads();
    }

    const float* resp = a.res[s];
    const float* biasp = a.bias[mat];
    float* outp = a.out[mat][s];
    #pragma unroll
    for (int mi = 0; mi < 2; mi++) {
        #pragma unroll
        for (int half = 0; half < 2; half++) {
            int m = m0 + wm + mi * 16 + g + half * 8;
            float bb = biasp[m];
            #pragma unroll
            for (int ni = 0; ni < 4; ni++) {
                int col = n0 + wn + ni * 8 + 2 * t;
                size_t off = ((size_t)b2 * M + m) * NN + col;
                float2 c;
                c.x = acc[mi][ni][2 * half + 0] + bb;
                c.y = acc[mi][ni][2 * half + 1] + bb;
                if (resp) {
                    float2 r = *(const float2*)(resp + off);
                    c.x += r.x; c.y += r.y;
                }
                *(float2*)(outp + off) = c;
            }
        }
    }
}

// ---------------------------------------------------------------------------
// Tensor-core flash attention (3xTF32), 64-q tiles, software-pipelined:
//  - Qh/Ql pre-split once into smem
//  - K double-buffered (Ks0/Ks1), V single-buffered, cp.async wait_group 1
//  - P raw single buffer, split at PV fragment load; V kept [d][k]
// Buffers (stride 68): Qh | Ql | Ks0 | Ks1 | Vs | Ps = 6*4352 floats
//   = 104448 B -> 2 blocks/SM.
// Per-thread commit FIFO: ... K[t], V[t], K[t+1], V[t+1] ...
//   iter-t top:  wait_group 1 -> K[t] done (V[t] may fly)
//   pre-PV:      wait_group 1 -> V[t] done (K[t+1] may fly)   (t=15: wg 0)
// ---------------------------------------------------------------------------
#define ATTN_SMEM (6 * 64 * 68 * 4)

__global__ __launch_bounds__(256) void attn_kernel() {
    extern __shared__ __align__(16) float sm[];
    float (*Qh)[68]  = (float(*)[68])(sm);              // [d][q] hi (scaled)
    float (*Ql)[68]  = (float(*)[68])(sm + 4352);       // [d][q] lo
    float (*Ks0)[68] = (float(*)[68])(sm + 2 * 4352);   // [d][k] buf 0
    float (*Ks1)[68] = (float(*)[68])(sm + 3 * 4352);   // [d][k] buf 1
    float (*Vs)[68]  = (float(*)[68])(sm + 4 * 4352);   // [d][k]
    float (*Ps)[68]  = (float(*)[68])(sm + 5 * 4352);   // [q][k] raw P; then [d][q] out
    __shared__ float red_max[2][4][16];
    __shared__ float red_sum[2][4][16];

    const int qt = blockIdx.x;
    const int bh = blockIdx.y;
    const int s  = blockIdx.z;
    const int b2 = bh >> 2, h = bh & 3;
    const int q0 = qt << 6;
    const int tid = threadIdx.x;
    const int warp = tid >> 5, lane = tid & 31;
    const int g = lane >> 2, t = lane & 3;
    const int qw = warp >> 1, kw = warp & 1;
    const int qcol = qw << 4;        // warp q base
    const int kcol = kw << 5;        // warp k base (S) == warp d base (PV)

    size_t base = (size_t)s * TEN + (size_t)b2 * (DD * NN);
    const float* __restrict__ qp = g_q + base;
    const float* __restrict__ kp = g_k + base;
    const float* __restrict__ vp = g_v + base;
    float* mp = g_msg + base;

    // load Q tile [d][q], fold 1/8 scale, split once
    for (int e = tid; e < 4096; e += 256) {
        int qi = e & 63, d = e >> 6;
        float v = qp[(size_t)(d * 4 + h) * NN + q0 + qi] * 0.125f;
        float hi = to_tf32(v);
        Qh[d][qi] = hi;
        Ql[d][qi] = v - hi;
    }

    // prologue: issue K[0] into Ks0 (group), V[0] into Vs (group)
    for (int e = tid; e < 1024; e += 256) {
        int d  = e >> 4;
        int c4 = (e & 15) << 2;
        cpa16(&Ks0[d][c4], kp + (size_t)(d * 4 + h) * NN + c4);
    }
    asm volatile("cp.async.commit_group;" ::: "memory");
    for (int e = tid; e < 1024; e += 256) {
        int d  = e >> 4;
        int c4 = (e & 15) << 2;
        cpa16(&Vs[d][c4], vp + (size_t)(d * 4 + h) * NN + c4);
    }
    asm volatile("cp.async.commit_group;" ::: "memory");

    float oacc[4][4] = {};
    float mi2[2] = {-1e30f, -1e30f};
    float li2[2] = {0.f, 0.f};

    for (int kt = 0; kt < 16; kt++) {
        float (*Kb)[68] = (kt & 1) ? Ks1 : Ks0;
        float (*Kn)[68] = (kt & 1) ? Ks0 : Ks1;

        asm volatile("cp.async.wait_group 1;" ::: "memory");  // K[kt] done
        __syncthreads();   // K visible to all; Q visible (kt=0); Kn free (read in kt-1)

        // issue K[kt+1] into the other buffer (overlaps S + softmax + PV)
        if (kt + 1 < 16) {
            int m1 = (kt + 1) << 6;
            for (int e = tid; e < 1024; e += 256) {
                int d  = e >> 4;
                int c4 = (e & 15) << 2;
                cpa16(&Kn[d][c4], kp + (size_t)(d * 4 + h) * NN + m1 + c4);
            }
            asm volatile("cp.async.commit_group;" ::: "memory");
        }

        // ----- S = Q^T K (3xTF32), warp tile 16q x 32k -----
        float sacc[4][4] = {};
        #pragma unroll
        for (int kk = 0; kk < 64; kk += 8) {
            unsigned ah[4], al[4];
            ah[0] = __float_as_uint(Qh[kk + t    ][qcol + g    ]);
            ah[1] = __float_as_uint(Qh[kk + t    ][qcol + g + 8]);
            ah[2] = __float_as_uint(Qh[kk + t + 4][qcol + g    ]);
            ah[3] = __float_as_uint(Qh[kk + t + 4][qcol + g + 8]);
            al[0] = __float_as_uint(Ql[kk + t    ][qcol + g    ]);
            al[1] = __float_as_uint(Ql[kk + t    ][qcol + g + 8]);
            al[2] = __float_as_uint(Ql[kk + t + 4][qcol + g    ]);
            al[3] = __float_as_uint(Ql[kk + t + 4][qcol + g + 8]);
            #pragma unroll
            for (int ni = 0; ni < 4; ni++) {
                int c = kcol + ni * 8 + g;
                float b0 = Kb[kk + t    ][c];
                float b1 = Kb[kk + t + 4][c];
                float h0 = to_tf32(b0), h1 = to_tf32(b1);
                unsigned bh2[2] = {__float_as_uint(h0), __float_as_uint(h1)};
                unsigned bl2[2] = {__float_as_uint(b0 - h0), __float_as_uint(b1 - h1)};
                MMA_TF32(sacc[ni], ah, bl2);
                MMA_TF32(sacc[ni], al, bh2);
                MMA_TF32(sacc[ni], ah, bh2);
            }
        }

        // ----- online softmax -----
        float mloc[2] = {-1e30f, -1e30f};
        #pragma unroll
        for (int ni = 0; ni < 4; ni++) {
            mloc[0] = fmaxf(mloc[0], fmaxf(sacc[ni][0], sacc[ni][1]));
            mloc[1] = fmaxf(mloc[1], fmaxf(sacc[ni][2], sacc[ni][3]));
        }
        #pragma unroll
        for (int r = 0; r < 2; r++) {
            mloc[r] = fmaxf(mloc[r], __shfl_xor_sync(0xffffffffu, mloc[r], 1));
            mloc[r] = fmaxf(mloc[r], __shfl_xor_sync(0xffffffffu, mloc[r], 2));
        }
        if (t == 0) {
            red_max[kw][qw][g    ] = mloc[0];
            red_max[kw][qw][g + 8] = mloc[1];
        }
        __syncthreads();
        float mn[2], alpha[2];
        #pragma unroll
        for (int r = 0; r < 2; r++) {
            int row = g + r * 8;
            float mk = fmaxf(red_max[0][qw][row], red_max[1][qw][row]);
            mn[r] = fmaxf(mi2[r], mk);
            alpha[r] = expq(mi2[r] - mn[r]);
            mi2[r] = mn[r];
        }
        float rs[2] = {0.f, 0.f};
        #pragma unroll
        for (int ni = 0; ni < 4; ni++) {
            #pragma unroll
            for (int j = 0; j < 4; j++) {
                int r = j >> 1;
                float p = expq(sacc[ni][j] - mn[r]);
                sacc[ni][j] = p;
                rs[r] += p;
            }
        }
        #pragma unroll
        for (int r = 0; r < 2; r++) {
            rs[r] += __shfl_xor_sync(0xffffffffu, rs[r], 1);
            rs[r] += __shfl_xor_sync(0xffffffffu, rs[r], 2);
        }
        if (t == 0) {
            red_sum[kw][qw][g    ] = rs[0];
            red_sum[kw][qw][g + 8] = rs[1];
        }
        // stage raw P [q][k]
        #pragma unroll
        for (int ni = 0; ni < 4; ni++) {
            #pragma unroll
            for (int r = 0; r < 2; r++) {
                int row = qcol + g + r * 8;
                int col = kcol + ni * 8 + 2 * t;
                *(float2*)&Ps[row][col] = make_float2(sacc[ni][2 * r], sacc[ni][2 * r + 1]);
            }
        }
        // V[kt] must be resident before PV (issued one iter ago -> hidden)
        if (kt + 1 < 16) {
            asm volatile("cp.async.wait_group 1;" ::: "memory");  // V[kt] done, K[kt+1] in flight
        } else {
            asm volatile("cp.async.wait_group 0;" ::: "memory");  // last V
        }
        __syncthreads();   // Ps + red_sum + Vs visible

        #pragma unroll
        for (int r = 0; r < 2; r++) {
            int row = g + r * 8;
            float rstot = red_sum[0][qw][row] + red_sum[1][qw][row];
            li2[r] = li2[r] * alpha[r] + rstot;
        }
        // rescale O
        #pragma unroll
        for (int ni = 0; ni < 4; ni++) {
            oacc[ni][0] *= alpha[0]; oacc[ni][1] *= alpha[0];
            oacc[ni][2] *= alpha[1]; oacc[ni][3] *= alpha[1];
        }

        // ----- O += P V (3xTF32), warp tile 16q x 32d, full 64 k -----
        #pragma unroll
        for (int kk = 0; kk < 64; kk += 8) {
            float a0 = Ps[qcol + g    ][kk + t    ];
            float a1 = Ps[qcol + g + 8][kk + t    ];
            float a2 = Ps[qcol + g    ][kk + t + 4];
            float a3 = Ps[qcol + g + 8][kk + t + 4];
            float ah0 = to_tf32(a0), ah1 = to_tf32(a1);
            float ah2 = to_tf32(a2), ah3 = to_tf32(a3);
            unsigned ah[4] = {__float_as_uint(ah0), __float_as_uint(ah1),
                              __float_as_uint(ah2), __float_as_uint(ah3)};
            unsigned al[4] = {__float_as_uint(a0 - ah0), __float_as_uint(a1 - ah1),
                              __float_as_uint(a2 - ah2), __float_as_uint(a3 - ah3)};
            #pragma unroll
            for (int ni = 0; ni < 4; ni++) {
                int c = kcol + ni * 8 + g;   // d column
                float b0 = Vs[c][kk + t    ];
                float b1 = Vs[c][kk + t + 4];
                float h0 = to_tf32(b0), h1 = to_tf32(b1);
                unsigned bh2[2] = {__float_as_uint(h0), __float_as_uint(h1)};
                unsigned bl2[2] = {__float_as_uint(b0 - h0), __float_as_uint(b1 - h1)};
                MMA_TF32(oacc[ni], ah, bl2);
                MMA_TF32(oacc[ni], al, bh2);
                MMA_TF32(oacc[ni], ah, bh2);
            }
        }

        __syncthreads();   // all PV reads of Vs/Ps done
        // issue V[kt+1] into Vs (overlaps next iter's S + softmax)
        if (kt + 1 < 16) {
            int m1 = (kt + 1) << 6;
            for (int e = tid; e < 1024; e += 256) {
                int d  = e >> 4;
                int c4 = (e & 15) << 2;
                cpa16(&Vs[d][c4], vp + (size_t)(d * 4 + h) * NN + m1 + c4);
            }
            asm volatile("cp.async.commit_group;" ::: "memory");
        }
    }

    // ----- epilogue: divide by li, stage [d][q] in Ps, coalesced store -----
    float inv[2] = {1.f / li2[0], 1.f / li2[1]};
    #pragma unroll
    for (int ni = 0; ni < 4; ni++) {
        #pragma unroll
        for (int j = 0; j < 4; j++) {
            int r = j >> 1;
            int row_q = qcol + g + r * 8;
            int col_d = kcol + ni * 8 + 2 * t + (j & 1);
            Ps[col_d][row_q] = oacc[ni][j] * inv[r];
        }
    }
    __syncthreads();
    for (int e = tid; e < 4096; e += 256) {
        int qi = e & 63, d = e >> 6;
        mp[(size_t)(d * 4 + h) * NN + q0 + qi] = Ps[d][qi];
    }
}

// ---------------------------------------------------------------------------
// BatchNorm stats (unchanged).
// ---------------------------------------------------------------------------
__global__ __launch_bounds__(256) void bn_stats_kernel(const float* __restrict__ g1,
                                                       const float* __restrict__ be1) {
    const int c = blockIdx.x;
    const int s = blockIdx.y;
    const float* hp = g_h + (size_t)s * HTEN;
    int tid = threadIdx.x;
    float sum = 0.f, sq = 0.f;
    for (int idx = tid; idx < 2048; idx += 256) {
        int b2 = idx >> 10, n = idx & 1023;
        float v = hp[((size_t)b2 * 512 + c) * NN + n];
        sum += v;
        sq = fmaf(v, v, sq);
    }
    #pragma unroll
    for (int w = 16; w; w >>= 1) {
        sum += __shfl_xor_sync(0xffffffffu, sum, w);
        sq  += __shfl_xor_sync(0xffffffffu, sq,  w);
    }
    __shared__ float ssum[8], ssq[8];
    int wid = tid >> 5, lane = tid & 31;
    if (lane == 0) { ssum[wid] = sum; ssq[wid] = sq; }
    __syncthreads();
    if (tid == 0) {
        float S = 0.f, Q = 0.f;
        #pragma unroll
        for (int i = 0; i < 8; i++) { S += ssum[i]; Q += ssq[i]; }
        float mean = S * (1.f / 2048.f);
        float var  = Q * (1.f / 2048.f) - mean * mean;
        float rstd = rsqrtf(var + 1e-5f);
        float sc = rstd * g1[c];
        float sh = be1[c] - mean * sc;
        g_stats[(s * 512 + c) * 2 + 0] = sc;
        g_stats[(s * 512 + c) * 2 + 1] = sh;
    }
}

// ---------------------------------------------------------------------------
// Host orchestration
// ---------------------------------------------------------------------------
extern "C" void kernel_launch(void* const* d_in, const int* in_sizes, int n_in,
                              void* d_out, int out_size) {
    const float* desc0 = (const float*)d_in[0];
    const float* desc1 = (const float*)d_in[1];
    const float* Wq  = (const float*)d_in[2];
    const float* bq  = (const float*)d_in[3];
    const float* Wk  = (const float*)d_in[4];
    const float* bk  = (const float*)d_in[5];
    const float* Wv  = (const float*)d_in[6];
    const float* bv  = (const float*)d_in[7];
    const float* Wm  = (const float*)d_in[8];
    const float* bm  = (const float*)d_in[9];
    const float* W1  = (const float*)d_in[10];
    const float* b1  = (const float*)d_in[11];
    const float* g1  = (const float*)d_in[12];
    const float* be1 = (const float*)d_in[13];
    const float* W2  = (const float*)d_in[14];
    const float* b2  = (const float*)d_in[15];
    float* out = (float*)d_out;

    float *qb, *kb, *vb, *msgb, *mmb, *hb, *statsb, *whi, *wlo;
    cudaGetSymbolAddress((void**)&qb,    g_q);
    cudaGetSymbolAddress((void**)&kb,    g_k);
    cudaGetSymbolAddress((void**)&vb,    g_v);
    cudaGetSymbolAddress((void**)&msgb,  g_msg);
    cudaGetSymbolAddress((void**)&mmb,   g_mm);
    cudaGetSymbolAddress((void**)&hb,    g_h);
    cudaGetSymbolAddress((void**)&statsb, g_stats);
    cudaGetSymbolAddress((void**)&whi,   g_whi);
    cudaGetSymbolAddress((void**)&wlo,   g_wlo);

    cudaFuncSetAttribute(attn_kernel,
                         cudaFuncAttributeMaxDynamicSharedMemorySize, ATTN_SMEM);
    cudaFuncSetAttribute(gemm_tc,
                         cudaFuncAttributeMaxDynamicSharedMemorySize, GEMM_SMEM);

    presplit_kernel<<<(int)((TOTW / 4 + 255) / 256), 256>>>(Wq, Wk, Wv, Wm, W1, W2);

    cudaMemcpyAsync(out + 2 * (size_t)TEN, desc0, TEN * sizeof(float),
                    cudaMemcpyDeviceToDevice, 0);
    cudaMemcpyAsync(out + 3 * (size_t)TEN, desc1, TEN * sizeof(float),
                    cudaMemcpyDeviceToDevice, 0);

    const float* xa = desc0;
    const float* xb = desc1;

    for (int i = 0; i < 18; i++) {
        const float *sa, *sb, *ra, *rb;
        float *oa, *ob;
        if (i == 0) {
            sa = xa; sb = xb; ra = desc0; rb = desc1;
            oa = out;            ob = out + (size_t)TEN;
        } else if (i == 1) {
            sa = xb; sb = xa; ra = desc0; rb = desc1;
            oa = out + 4 * (size_t)TEN; ob = out + 5 * (size_t)TEN;
        } else {
            if ((i & 1) == 0) { sa = xa; sb = xb; }
            else              { sa = xb; sb = xa; }
            ra = xa; rb = xb;
            oa = out + (size_t)(2 + 2 * i) * TEN;
            ob = oa + (size_t)TEN;
        }

        const float* Wq_hi = whi + OFF_WQ + (size_t)i * 65536;
        const float* Wq_lo = wlo + OFF_WQ + (size_t)i * 65536;
        const float* Wk_hi = whi + OFF_WK + (size_t)i * 65536;
        const float* Wk_lo = wlo + OFF_WK + (size_t)i * 65536;
        const float* Wv_hi = whi + OFF_WV + (size_t)i * 65536;
        const float* Wv_lo = wlo + OFF_WV + (size_t)i * 65536;
        const float* Wm_hi = whi + OFF_WM + (size_t)i * 65536;
        const float* Wm_lo = wlo + OFF_WM + (size_t)i * 65536;
        const float* W1_hi = whi + OFF_W1 + (size_t)i * 262144;
        const float* W1_lo = wlo + OFF_W1 + (size_t)i * 262144;
        const float* W2_hi = whi + OFF_W2 + (size_t)i * 131072;
        const float* W2_lo = wlo + OFF_W2 + (size_t)i * 131072;
        const float* bq_i = bq + (size_t)i * 256;
        const float* bk_i = bk + (size_t)i * 256;
        const float* bv_i = bv + (size_t)i * 256;
        const float* bm_i = bm + (size_t)i * 256;
        const float* b1_i = b1 + (size_t)i * 512;
        const float* b2_i = b2 + (size_t)i * 256;
        const float* g1_i = g1 + (size_t)i * 512;
        const float* be_i = be1 + (size_t)i * 512;

        GArgs ga = {};
        ga.bnp[0] = statsb; ga.bnp[1] = statsb + 1024;

        // q/k/v merged
        ga.Whi[0] = Wq_hi; ga.Wlo[0] = Wq_lo; ga.bias[0] = bq_i;
        ga.Whi[1] = Wk_hi; ga.Wlo[1] = Wk_lo; ga.bias[1] = bk_i;
        ga.Whi[2] = Wv_hi; ga.Wlo[2] = Wv_lo; ga.bias[2] = bv_i;
        ga.X0[0][0] = xa; ga.X0[0][1] = xb;
        ga.X0[1][0] = sa; ga.X0[1][1] = sb;
        ga.X0[2][0] = sa; ga.X0[2][1] = sb;
        ga.out[0][0] = qb; ga.out[0][1] = qb + TEN;
        ga.out[1][0] = kb; ga.out[1][1] = kb + TEN;
        ga.out[2][0] = vb; ga.out[2][1] = vb + TEN;
        ga.X1[0] = ga.X1[1] = nullptr;
        ga.res[0] = ga.res[1] = nullptr;
        ga.M = 256; ga.K = 256; ga.K0 = 256; ga.use_bn = 0; ga.mtiles = 4;
        gemm_tc<<<dim3(32, 12, 2), 128, GEMM_SMEM>>>(ga);

        // attention
        attn_kernel<<<dim3(16, 8, 2), 256, ATTN_SMEM>>>();

        // msg projection
        ga.Whi[0] = Wm_hi; ga.Wlo[0] = Wm_lo; ga.bias[0] = bm_i;
        ga.X0[0][0] = msgb; ga.X0[0][1] = msgb + TEN;
        ga.out[0][0] = mmb; ga.out[0][1] = mmb + TEN;
        ga.M = 256; ga.K = 256; ga.K0 = 256; ga.use_bn = 0; ga.mtiles = 4;
        gemm_tc<<<dim3(32, 4, 2), 128, GEMM_SMEM>>>(ga);

        // h = W1 [x; msg] + b1
        ga.Whi[0] = W1_hi; ga.Wlo[0] = W1_lo; ga.bias[0] = b1_i;
        ga.X0[0][0] = xa; ga.X0[0][1] = xb;
        ga.X1[0] = mmb; ga.X1[1] = mmb + TEN;
        ga.out[0][0] = hb; ga.out[0][1] = hb + HTEN;
        ga.M = 512; ga.K = 512; ga.K0 = 256; ga.use_bn = 0; ga.mtiles = 8;
        gemm_tc<<<dim3(32, 8, 2), 128, GEMM_SMEM>>>(ga);

        // BN stats
        bn_stats_kernel<<<dim3(512, 2), 256>>>(g1_i, be_i);

        // out = res + W2 relu(BN(h)) + b2
        ga.Whi[0] = W2_hi; ga.Wlo[0] = W2_lo; ga.bias[0] = b2_i;
        ga.X0[0][0] = hb; ga.X0[0][1] = hb + HTEN;
        ga.X1[0] = ga.X1[1] = nullptr;
        ga.res[0] = ra; ga.res[1] = rb;
        ga.out[0][0] = oa; ga.out[0][1] = ob;
        ga.M = 256; ga.K = 512; ga.K0 = 512; ga.use_bn = 1; ga.mtiles = 4;
        gemm_tc<<<dim3(32, 4, 2), 128, GEMM_SMEM>>>(ga);
        ga.res[0] = ga.res[1] = nullptr;

        xa = oa; xb = ob;
    }
}